// round 17
// baseline (speedup 1.0000x reference)
#include <cuda_runtime.h>
#include <cuda_fp16.h>
#include <cstdint>

#define NNODES 50000
#define FDIM   256
#define KMIX   5
#define EMAX   1700000
#define NBLK   196                          // ceil(NNODES/256)
#define PBLK   (NNODES / 4)                 // 12500 prep blocks (4 nodes each)

// ---------------- scratch ----------------
__device__ unsigned g_mbits[NNODES * 8];      // bit mask, 256 bits/node
__device__ float g_indeg[NNODES];
__device__ float g_gamma[NNODES * KMIX];
__device__ int   g_flags[2];
__device__ int   g_count[NNODES];
__device__ int   g_locs[NNODES];              // local exclusive scans
__device__ int   g_bsum[NBLK];
__device__ int   g_boff[NBLK + 1];
__device__ int   g_scandone;
__device__ int   g_sorted[EMAX];
__device__ float g_ivar[KMIX * FDIM];         // exp(-logvars)
__device__ float2 g_htab[1025];               // h(w): value, delta-per-interval
__device__ __half g_x0h[NNODES * FDIM];       // fp16 masked x (gather source)
__device__ __half g_S0h[NNODES * FDIM];       // fp16 aggregated S0
__device__ __half g_SMh[NNODES * FDIM];       // aggregated mask counts (exact fp16)
// B concat (single fp16): [group g (32 outs)][352 rows (n)][256 (k)]
__device__ __half g_B[8][352 * 256];

// ---------------- PTX helpers (baseline ISA only) ----------------
__device__ __forceinline__ uint32_t smem_u32(const void* p) {
    uint32_t a;
    asm("{ .reg .u64 t; cvta.to.shared.u64 t, %1; cvt.u32.u64 %0, t; }" : "=r"(a) : "l"(p));
    return a;
}
__device__ __forceinline__ void cpasync16(uint32_t dst, const void* src) {
    asm volatile("cp.async.cg.shared.global [%0], [%1], 16;" :: "r"(dst), "l"(src));
}
#define CP_COMMIT() asm volatile("cp.async.commit_group;" ::: "memory")
#define CP_WAIT1()  asm volatile("cp.async.wait_group 1;" ::: "memory")
#define CP_WAIT0()  asm volatile("cp.async.wait_group 0;" ::: "memory")

__device__ __forceinline__ void ldsm4(uint32_t* r, uint32_t addr) {
    asm volatile("ldmatrix.sync.aligned.m8n8.x4.shared.b16 {%0,%1,%2,%3}, [%4];"
                 : "=r"(r[0]), "=r"(r[1]), "=r"(r[2]), "=r"(r[3]) : "r"(addr));
}
__device__ __forceinline__ void mma16816(float* d, const uint32_t* a, const uint32_t* b) {
    asm volatile("mma.sync.aligned.m16n8k16.row.col.f32.f16.f16.f32 "
                 "{%0,%1,%2,%3}, {%4,%5,%6,%7}, {%8,%9}, {%0,%1,%2,%3};"
                 : "+f"(d[0]), "+f"(d[1]), "+f"(d[2]), "+f"(d[3])
                 : "r"(a[0]), "r"(a[1]), "r"(a[2]), "r"(a[3]), "r"(b[0]), "r"(b[1]));
}

// ---------------- launch 1: zero counters + global dtype detect --------
__global__ void zero_detect_kernel(const void* mask, const void* edges) {
    int b = blockIdx.x, t = threadIdx.x;
    if (b < NBLK) {
        int i = b * 256 + t;
        if (i < NNODES) g_count[i] = 0;
        if (b == 0 && t == 0) g_scandone = 0;
    } else {
        int any_m = 0, any_e = 0;
        const unsigned char* mb = (const unsigned char*)mask;
        const int* ei = (const int*)edges;
        for (int i = t; i < 4096; i += 256) {
            if (mb[4 * i + 1] != 0) any_m = 1;
            if (ei[2 * i + 1] != 0) any_e = 1;
        }
        any_m = __syncthreads_or(any_m);
        any_e = __syncthreads_or(any_e);
        if (t == 0) { g_flags[0] = any_m ? 1 : 0; g_flags[1] = any_e ? 0 : 1; }
    }
}

// ---------------- launch 2: megaprep = prep+x0h + count + bprep + ivar + htab
__device__ __forceinline__ float h_exact(float w) {
    return 0.3989422804014327f * expf(-0.5f * w * w)
         + 0.5f * w * (1.0f + erff(w * 0.7071067811865476f));
}

__global__ __launch_bounds__(256) void megaprep_kernel(
    const void* __restrict__ mask, const void* __restrict__ edges, int E, int eb,
    const float* __restrict__ x,
    const float* __restrict__ W, const float* __restrict__ means,
    const float* __restrict__ logvars)
{
    int b = blockIdx.x, t = threadIdx.x;
    if (b < PBLK) {
        // prep: 4 nodes/block, 64 threads/node, 4 features/thread
        int node = b * 4 + (t >> 6);
        int u = t & 63;
        int m0, m1, m2, m3;
        if (g_flags[0]) {
            uchar4 w = ((const uchar4*)mask)[node * 64 + u];
            m0 = w.x; m1 = w.y; m2 = w.z; m3 = w.w;
        } else {
            int4 w = ((const int4*)mask)[node * 64 + u];
            m0 = w.x; m1 = w.y; m2 = w.z; m3 = w.w;
        }
        unsigned nib = (m0 ? 1u : 0u) | (m1 ? 2u : 0u) | (m2 ? 4u : 0u) | (m3 ? 8u : 0u);
        unsigned v = nib << (4 * (t & 7));
        v |= __shfl_xor_sync(0xffffffffu, v, 1);
        v |= __shfl_xor_sync(0xffffffffu, v, 2);
        v |= __shfl_xor_sync(0xffffffffu, v, 4);
        if ((t & 7) == 0) g_mbits[node * 8 + (u >> 3)] = v;
        float4 xv = ((const float4*)x)[node * 64 + u];
        __half2 h01 = __floats2half2_rn(m0 ? 0.f : xv.x, m1 ? 0.f : xv.y);
        __half2 h23 = __floats2half2_rn(m2 ? 0.f : xv.z, m3 ? 0.f : xv.w);
        uint2 o;
        o.x = *(unsigned*)&h01;
        o.y = *(unsigned*)&h23;
        ((uint2*)g_x0h)[node * 64 + u] = o;
        return;
    }
    b -= PBLK;
    if (b < eb) {
        int i = b * 256 + t;
        if (i < E) {
            int dst = g_flags[1] ? (int)((const long long*)edges)[E + i]
                                 : ((const int*)edges)[E + i];
            atomicAdd(&g_count[dst], 1);
        }
        return;
    }
    b -= eb;
    if (b < 8 * 352) {
        // bprep
        int g = b / 352, n = b % 352;
        float val;
        if (n < 32) {
            val = W[t * FDIM + g * 32 + n];
        } else {
            int mat = (n - 32) >> 5;
            int o = g * 32 + ((n - 32) & 31);
            int k = mat >> 1;
            float w = W[t * FDIM + o];
            if ((mat & 1) == 0) val = means[k * FDIM + t] * w;
            else                val = expf(logvars[k * FDIM + t]) * w * w;
        }
        g_B[g][n * FDIM + t] = __float2half_rn(val);
        return;
    }
    b -= 8 * 352;
    if (b < 5) {
        int i = b * 256 + t;
        if (i < KMIX * FDIM) g_ivar[i] = expf(-logvars[i]);
        return;
    }
    b -= 5;
    {
        int i = b * 256 + t;
        if (i <= 1024) {
            float w0 = -8.0f + i * (1.0f / 64.0f);
            float h0 = h_exact(w0);
            float h1 = h_exact(w0 + (1.0f / 64.0f));
            g_htab[i] = make_float2(h0, h1 - h0);
        }
    }
}

// ---------------- scan: local scans + last-block does the block-sum scan
__global__ __launch_bounds__(256) void scan_kernel() {
    int b = blockIdx.x, t = threadIdx.x;
    int i = b * 256 + t;
    int v = (i < NNODES) ? g_count[i] : 0;
    __shared__ int sh[256];
    sh[t] = v;
    __syncthreads();
    for (int off = 1; off < 256; off <<= 1) {
        int u = (t >= off) ? sh[t - off] : 0;
        __syncthreads();
        sh[t] += u;
        __syncthreads();
    }
    if (i < NNODES) g_locs[i] = sh[t] - v;
    if (t == 255) g_bsum[b] = sh[255];

    // last block scans g_bsum -> g_boff
    __threadfence();
    __shared__ int isLast;
    if (t == 0) isLast = (atomicAdd(&g_scandone, 1) == NBLK - 1) ? 1 : 0;
    __syncthreads();
    if (!isLast) return;
    int w = (t < NBLK) ? g_bsum[t] : 0;
    sh[t] = w;
    __syncthreads();
    for (int off = 1; off < 256; off <<= 1) {
        int u = (t >= off) ? sh[t - off] : 0;
        __syncthreads();
        sh[t] += u;
        __syncthreads();
    }
    if (t < NBLK) g_boff[t] = sh[t] - w;
    if (t == 255) g_boff[NBLK] = sh[255];
}

__device__ __forceinline__ int node_offset(int n) {
    return (n < NNODES) ? (g_locs[n] + g_boff[n >> 8]) : g_boff[NBLK];
}

// ---------------- scatter (reverse fill via count decrement) ------------
__global__ void scatter_kernel(const void* __restrict__ edges, int E) {
    int i = blockIdx.x * blockDim.x + threadIdx.x;
    if (i >= E) return;
    int src, dst;
    if (g_flags[1]) {
        const long long* e = (const long long*)edges;
        src = (int)e[i]; dst = (int)e[E + i];
    } else {
        const int* e = (const int*)edges;
        src = e[i]; dst = e[E + i];
    }
    int pos = atomicAdd(&g_count[dst], -1) - 1;    // counts -> 0, reverse order
    g_sorted[g_locs[dst] + g_boff[dst >> 8] + pos] = src;
}

// ---------------- aggregate: 4 warps/block, 1 warp/node, uint4 gather ---
__global__ __launch_bounds__(128) void aggregate_kernel(
    const float* __restrict__ x, const float* __restrict__ logp,
    const float* __restrict__ means)
{
    int n = blockIdx.x * 4 + (threadIdx.x >> 5);
    int u = threadIdx.x & 31;              // lane, features 8u..8u+7
    int wsel = u >> 2;                     // mbits word
    int shift = 8 * (u & 3);               // byte within word

    int beg = node_offset(n), end = node_offset(n + 1);

    unsigned byte = (g_mbits[n * 8 + wsel] >> shift) & 0xffu;
    float4 xa = ((const float4*)x)[n * 64 + 2 * u];
    float4 xb = ((const float4*)x)[n * 64 + 2 * u + 1];
    float xs[8] = { xa.x, xa.y, xa.z, xa.w, xb.x, xb.y, xb.z, xb.w };

    float acc[8];
    int cnt[8];
#pragma unroll
    for (int j = 0; j < 8; j++) {
        int bj = (byte >> j) & 1;
        acc[j] = bj ? 0.f : xs[j];
        cnt[j] = bj;
    }

    // gamma logits partial (self x only)
    float q[KMIX];
#pragma unroll
    for (int k = 0; k < KMIX; k++) {
        float4 ma = ((const float4*)means)[k * 64 + 2 * u];
        float4 mb2 = ((const float4*)means)[k * 64 + 2 * u + 1];
        float4 ia = ((const float4*)g_ivar)[k * 64 + 2 * u];
        float4 ib = ((const float4*)g_ivar)[k * 64 + 2 * u + 1];
        float mk[8] = { ma.x, ma.y, ma.z, ma.w, mb2.x, mb2.y, mb2.z, mb2.w };
        float iv[8] = { ia.x, ia.y, ia.z, ia.w, ib.x, ib.y, ib.z, ib.w };
        float s = 0.f;
#pragma unroll
        for (int j = 0; j < 8; j++) {
            float d = xs[j] - mk[j];
            if (!((byte >> j) & 1)) s += d * d * iv[j];
        }
        q[k] = s;
    }

    __shared__ int ssrc[4][32];
    int* sw = ssrc[threadIdx.x >> 5];
    const uint4* x0 = (const uint4*)g_x0h;     // 32 uint4 per node row
    for (int chunk = beg; chunk < end; chunk += 32) {
        int nload = min(32, end - chunk);
        __syncwarp();
        if (u < nload) sw[u] = g_sorted[chunk + u];
        __syncwarp();
        int i = 0;
        for (; i + 2 <= nload; i += 2) {
            int s0 = sw[i], s1 = sw[i + 1];
            uint4 w0 = __ldg(&x0[(size_t)s0 * 32 + u]);
            uint4 w1 = __ldg(&x0[(size_t)s1 * 32 + u]);
            unsigned b0 = (__ldg(&g_mbits[s0 * 8 + wsel]) >> shift) & 0xffu;
            unsigned b1 = (__ldg(&g_mbits[s1 * 8 + wsel]) >> shift) & 0xffu;
            float2 a0 = __half22float2(*(__half2*)&w0.x);
            float2 a1 = __half22float2(*(__half2*)&w0.y);
            float2 a2 = __half22float2(*(__half2*)&w0.z);
            float2 a3 = __half22float2(*(__half2*)&w0.w);
            float2 c0 = __half22float2(*(__half2*)&w1.x);
            float2 c1 = __half22float2(*(__half2*)&w1.y);
            float2 c2 = __half22float2(*(__half2*)&w1.z);
            float2 c3 = __half22float2(*(__half2*)&w1.w);
            acc[0] += a0.x + c0.x;  acc[1] += a0.y + c0.y;
            acc[2] += a1.x + c1.x;  acc[3] += a1.y + c1.y;
            acc[4] += a2.x + c2.x;  acc[5] += a2.y + c2.y;
            acc[6] += a3.x + c3.x;  acc[7] += a3.y + c3.y;
#pragma unroll
            for (int j = 0; j < 8; j++)
                cnt[j] += ((b0 >> j) & 1) + ((b1 >> j) & 1);
        }
        if (i < nload) {
            int s0 = sw[i];
            uint4 w0 = __ldg(&x0[(size_t)s0 * 32 + u]);
            unsigned b0 = (__ldg(&g_mbits[s0 * 8 + wsel]) >> shift) & 0xffu;
            float2 a0 = __half22float2(*(__half2*)&w0.x);
            float2 a1 = __half22float2(*(__half2*)&w0.y);
            float2 a2 = __half22float2(*(__half2*)&w0.z);
            float2 a3 = __half22float2(*(__half2*)&w0.w);
            acc[0] += a0.x;  acc[1] += a0.y;
            acc[2] += a1.x;  acc[3] += a1.y;
            acc[4] += a2.x;  acc[5] += a2.y;
            acc[6] += a3.x;  acc[7] += a3.y;
#pragma unroll
            for (int j = 0; j < 8; j++) cnt[j] += (b0 >> j) & 1;
        }
    }

    {
        __half2 h0 = __floats2half2_rn(acc[0], acc[1]);
        __half2 h1 = __floats2half2_rn(acc[2], acc[3]);
        __half2 h2 = __floats2half2_rn(acc[4], acc[5]);
        __half2 h3 = __floats2half2_rn(acc[6], acc[7]);
        uint4 o;
        o.x = *(unsigned*)&h0; o.y = *(unsigned*)&h1;
        o.z = *(unsigned*)&h2; o.w = *(unsigned*)&h3;
        ((uint4*)g_S0h)[n * 32 + u] = o;
        __half2 c0 = __floats2half2_rn((float)cnt[0], (float)cnt[1]);
        __half2 c1 = __floats2half2_rn((float)cnt[2], (float)cnt[3]);
        __half2 c2 = __floats2half2_rn((float)cnt[4], (float)cnt[5]);
        __half2 c3 = __floats2half2_rn((float)cnt[6], (float)cnt[7]);
        uint4 c;
        c.x = *(unsigned*)&c0; c.y = *(unsigned*)&c1;
        c.z = *(unsigned*)&c2; c.w = *(unsigned*)&c3;
        ((uint4*)g_SMh)[n * 32 + u] = c;
    }
    if (u == 0) g_indeg[n] = (float)(end - beg);

    // gamma reduction + softmax (per warp)
#pragma unroll
    for (int k = 0; k < KMIX; k++)
        for (int off = 16; off; off >>= 1)
            q[k] += __shfl_down_sync(0xffffffffu, q[k], off);
    if (u == 0) {
        float l[KMIX], mx = -1e30f;
#pragma unroll
        for (int k = 0; k < KMIX; k++) {
            l[k] = logp[k] - 0.5f * q[k];
            mx = fmaxf(mx, l[k]);
        }
        float e[KMIX], se = 0.f;
#pragma unroll
        for (int k = 0; k < KMIX; k++) { e[k] = __expf(l[k] - mx); se += e[k]; }
        float inv = 1.0f / se;
#pragma unroll
        for (int k = 0; k < KMIX; k++) g_gamma[n * KMIX + k] = e[k] * inv;
    }
}

// ---------------- mma.sync GEMM (128-node tile, K64 chunks) -------------
__device__ __forceinline__ float ex_relu_tab(float mu, float s, const float2* htab) {
    if (s <= 0.0f) return fmaxf(mu, 0.0f);
    float rs = rsqrtf(s);
    float w  = mu * rs;
    if (w >= 8.0f) return mu;
    if (w <= -8.0f) return 0.0f;
    float ss = s * rs;               // = sqrt(s)
    float p = (w + 8.0f) * 64.0f;
    int i = (int)p;
    float frac = p - (float)i;
    float2 e = htab[i];
    return ss * fmaf(frac, e.y, e.x);
}

// SMEM layout (per buffer), 144-byte row pitch (64 halfs + pad; 144/16=9 odd -> conflict-free ldsm)
#define PITCH   144
#define OFF_A0H 0
#define OFF_AMH (128 * PITCH)             // 18432
#define OFF_B   (2 * 128 * PITCH)         // 36864
#define BUFSZ   (2 * 128 * PITCH + 352 * PITCH)   // 87552
#define OFF_HTAB (2 * BUFSZ)              // 175104
#define SM_TOTAL (2 * BUFSZ + 8224)       // 183328

__device__ __forceinline__ void load_chunk(uint32_t sbuf, int nb, int g, int kc) {
    int t = threadIdx.x;                   // 512 threads
    const char* srcA0 = (const char*)g_S0h;
    const char* srcA2 = (const char*)g_SMh;
    const char* bp = (const char*)&g_B[g][0];
    // A: 2 tiles x 128 rows x 8 c16 = 2048; B: 352 x 8 = 2816; total 4864
    for (int id = t; id < 4864; id += 512) {
        if (id < 2048) {
            int tile = id >> 10, rem = id & 1023;
            int row = rem >> 3, c16 = rem & 7;
            int node = nb + row; if (node >= NNODES) node = NNODES - 1;
            const char* base = tile == 0 ? srcA0 : srcA2;
            const char* src = base + ((size_t)node * FDIM + kc * 64 + c16 * 8) * 2;
            uint32_t dst = sbuf + OFF_A0H + tile * (128 * PITCH) + row * PITCH + c16 * 16;
            cpasync16(dst, src);
        } else {
            int rem = id - 2048;
            int row = rem >> 3, c16 = rem & 7;
            const char* src = bp + ((size_t)row * FDIM + kc * 64 + c16 * 8) * 2;
            uint32_t dst = sbuf + OFF_B + row * PITCH + c16 * 16;
            cpasync16(dst, src);
        }
    }
}

__global__ __launch_bounds__(512, 1) void gemm_mma_kernel(
    const float* __restrict__ bias, float* __restrict__ out)
{
    extern __shared__ char smem[];
    uint32_t sb = smem_u32(smem);
    int t = threadIdx.x;
    int lane = t & 31, wid = t >> 5;
    int wm = wid & 7, wn = wid >> 3;          // 8 m-tiles x 2 n-tiles
    int nb = blockIdx.y * 128;                // node tile (128 nodes)
    int g  = blockIdx.x;                      // group — A reuse in-wave
    int ob = g * 32;

    // copy h-table into smem (ordered by the first __syncthreads below)
    float2* htab = (float2*)(smem + OFF_HTAB);
    for (int i = t; i < 1025; i += 512) htab[i] = g_htab[i];

    float acc[11][8];
#pragma unroll
    for (int a = 0; a < 11; a++)
#pragma unroll
        for (int d = 0; d < 8; d++) acc[a][d] = 0.0f;

    load_chunk(sb, nb, g, 0);
    CP_COMMIT();

    int arow = wm * 16 + (lane & 15);
    int acolsel = (lane >> 4) << 3;
    int brow = wn * 16 + (lane & 7) + ((lane >> 4) << 3);
    int bcolsel = ((lane >> 3) & 1) << 3;

    for (int c = 0; c < 4; c++) {
        if (c < 3) { load_chunk(sb + ((c + 1) & 1) * BUFSZ, nb, g, c + 1); CP_COMMIT(); CP_WAIT1(); }
        else CP_WAIT0();
        __syncthreads();

        uint32_t b32 = sb + (c & 1) * BUFSZ;
#pragma unroll
        for (int j = 0; j < 4; j++) {
            uint32_t aoff = (uint32_t)(arow * PITCH + (j * 16 + acolsel) * 2);
            uint32_t aH[4], aM[4];
            ldsm4(aH, b32 + OFF_A0H + aoff);
            ldsm4(aM, b32 + OFF_AMH + aoff);

            uint32_t boff0 = (uint32_t)(brow * PITCH + (j * 16 + bcolsel) * 2);
            uint32_t bq[4];
            // t0 path: S0h * B
            ldsm4(bq, b32 + OFF_B + boff0);
            mma16816(&acc[0][0], aH, &bq[0]); mma16816(&acc[0][4], aH, &bq[2]);
            // SM path: counts * B  (counts exact in fp16)
#pragma unroll
            for (int a = 1; a <= 10; a++) {
                uint32_t boff = boff0 + (uint32_t)(a * 32 * PITCH);
                ldsm4(bq, b32 + OFF_B + boff);
                mma16816(&acc[a][0], aM, &bq[0]); mma16816(&acc[a][4], aM, &bq[2]);
            }
        }
        __syncthreads();
    }

    int r0 = lane >> 2, c0 = (lane & 3) * 2;
#pragma unroll
    for (int i = 0; i < 2; i++) {
        int node = nb + wm * 16 + r0 + i * 8;
        if (node >= NNODES) continue;
        float deg1 = 1.0f + g_indeg[node];
        float gam[KMIX];
#pragma unroll
        for (int k = 0; k < KMIX; k++) gam[k] = g_gamma[node * KMIX + k];
#pragma unroll
        for (int f = 0; f < 2; f++) {
            int o = ob + wn * 16 + f * 8 + c0;
            float bb0 = bias[o] * deg1;
            float bb1 = bias[o + 1] * deg1;
            int d = f * 4 + i * 2;
            float mu0 = acc[0][d], mu1 = acc[0][d + 1];
            float s0 = 0.f, s1 = 0.f;
#pragma unroll
            for (int k = 0; k < KMIX; k++) {
                s0 += gam[k] * ex_relu_tab(mu0 + acc[1 + 2 * k][d] + bb0,     acc[2 + 2 * k][d],     htab);
                s1 += gam[k] * ex_relu_tab(mu1 + acc[1 + 2 * k][d + 1] + bb1, acc[2 + 2 * k][d + 1], htab);
            }
            *(float2*)&out[(size_t)node * FDIM + o] = make_float2(s0, s1);
        }
    }
}

// ---------------- launcher ----------------
extern "C" void kernel_launch(void* const* d_in, const int* in_sizes, int n_in,
                              void* d_out, int out_size) {
    const float* x       = (const float*)d_in[0];
    const void*  edges   = d_in[1];
    const void*  mask    = d_in[2];
    const float* logp    = (const float*)d_in[3];
    const float* means   = (const float*)d_in[4];
    const float* logvars = (const float*)d_in[5];
    const float* W       = (const float*)d_in[6];
    const float* bias    = (const float*)d_in[7];
    float* out = (float*)d_out;

    int E = in_sizes[1] / 2;
    int eb = (E + 255) / 256;

    cudaFuncSetAttribute(gemm_mma_kernel, cudaFuncAttributeMaxDynamicSharedMemorySize, SM_TOTAL);

    zero_detect_kernel<<<NBLK + 1, 256>>>(mask, edges);
    megaprep_kernel<<<PBLK + eb + 8 * 352 + 10, 256>>>(mask, edges, E, eb, x, W, means, logvars);
    scan_kernel<<<NBLK, 256>>>();
    scatter_kernel<<<eb, 256>>>(edges, E);
    aggregate_kernel<<<(NNODES + 3) / 4, 128>>>(x, logp, means);

    dim3 ggrid(8, (NNODES + 127) / 128);
    gemm_mma_kernel<<<ggrid, 512, SM_TOTAL>>>(bias, out);
}